// round 1
// baseline (speedup 1.0000x reference)
#include <cuda_runtime.h>
#include <math.h>

#define NDIN 25
#define NDP 128
#define NROWS (256*2048)
#define WARPS 8
#define RPW 4
#define ROWS_PER_CTA (WARPS*RPW)   // 32
#define NBLKS (NROWS/ROWS_PER_CTA) // 16384
#define GRID 296                   // 2 CTAs/SM * 148 SMs, persistent

struct __align__(16) Smem {
    float w1[NDIN][NDP];      // 12800 B
    float w2[NDP][NDP];       // 65536 B
    float b1[NDP];            // 512 B
    float b2[NDP];            // 512 B
    float xn[WARPS][NDIN][RPW]; // [d][r] so a float4 broadcast gives 4 rows' xn at dim d
    float h[WARPS][RPW][NDP];   // [r][p] row-major, conflict-free STS.128
};

__device__ __forceinline__ float gelu_exact(float v) {
    return 0.5f * v * (1.0f + erff(v * 0.70710678118654752440f));
}

__global__ __launch_bounds__(256, 2)
void ip_kernel(const float* __restrict__ x,
               const float* __restrict__ ln_g,
               const float* __restrict__ ln_b,
               const float* __restrict__ w1,
               const float* __restrict__ b1,
               const float* __restrict__ w2,
               const float* __restrict__ b2,
               float* __restrict__ out) {
    extern __shared__ char smem_raw[];
    Smem& s = *reinterpret_cast<Smem*>(smem_raw);
    const int tid = threadIdx.x;

    // ---- cooperative weight staging (once per persistent CTA) ----
    {
        float4* dst1 = reinterpret_cast<float4*>(&s.w1[0][0]);
        const float4* src1 = reinterpret_cast<const float4*>(w1);
        for (int i = tid; i < NDIN * NDP / 4; i += blockDim.x) dst1[i] = src1[i];
        float4* dst2 = reinterpret_cast<float4*>(&s.w2[0][0]);
        const float4* src2 = reinterpret_cast<const float4*>(w2);
        for (int i = tid; i < NDP * NDP / 4; i += blockDim.x) dst2[i] = src2[i];
        if (tid < NDP / 4) {
            reinterpret_cast<float4*>(s.b1)[tid] = reinterpret_cast<const float4*>(b1)[tid];
            reinterpret_cast<float4*>(s.b2)[tid] = reinterpret_cast<const float4*>(b2)[tid];
        }
    }
    __syncthreads();

    const int w = tid >> 5;
    const int l = tid & 31;
    const float gam = (l < NDIN) ? ln_g[l] : 0.0f;
    const float bet = (l < NDIN) ? ln_b[l] : 0.0f;
    const float4 b1v = *reinterpret_cast<const float4*>(&s.b1[4 * l]);
    const float4 b2v = *reinterpret_cast<const float4*>(&s.b2[4 * l]);

    for (int blk = blockIdx.x; blk < NBLKS; blk += gridDim.x) {
        const long base = (long)blk * ROWS_PER_CTA + (long)w * RPW;

        // ---- load 4 rows of x (lane l holds x[row][l], l<25) ----
        float xv[RPW];
        #pragma unroll
        for (int r = 0; r < RPW; r++)
            xv[r] = (l < NDIN) ? x[(base + r) * NDIN + l] : 0.0f;

        // ---- LayerNorm: two-pass (mean, then centered var) ----
        float sum[RPW];
        #pragma unroll
        for (int r = 0; r < RPW; r++) sum[r] = xv[r];
        #pragma unroll
        for (int o = 16; o > 0; o >>= 1) {
            #pragma unroll
            for (int r = 0; r < RPW; r++)
                sum[r] += __shfl_xor_sync(0xffffffffu, sum[r], o);
        }
        float dcen[RPW], sq[RPW];
        #pragma unroll
        for (int r = 0; r < RPW; r++) {
            float mu = sum[r] * (1.0f / NDIN);
            dcen[r] = (l < NDIN) ? (xv[r] - mu) : 0.0f;
            sq[r] = dcen[r] * dcen[r];
        }
        #pragma unroll
        for (int o = 16; o > 0; o >>= 1) {
            #pragma unroll
            for (int r = 0; r < RPW; r++)
                sq[r] += __shfl_xor_sync(0xffffffffu, sq[r], o);
        }
        float xnv[RPW];
        #pragma unroll
        for (int r = 0; r < RPW; r++) {
            float rstd = rsqrtf(sq[r] * (1.0f / NDIN) + 1e-5f);
            xnv[r] = dcen[r] * rstd * gam + bet;
        }
        if (l < NDIN) {
            float4 q = make_float4(xnv[0], xnv[1], xnv[2], xnv[3]);
            *reinterpret_cast<float4*>(&s.xn[w][l][0]) = q;
        }
        __syncwarp();

        // ---- GEMM1: h[r][p] = xn[r] @ w1, lane l owns p in [4l, 4l+4) ----
        float acc1[RPW][4];
        #pragma unroll
        for (int r = 0; r < RPW; r++)
            #pragma unroll
            for (int j = 0; j < 4; j++) acc1[r][j] = 0.0f;

        #pragma unroll
        for (int d = 0; d < NDIN; d++) {
            float4 wv = *reinterpret_cast<const float4*>(&s.w1[d][4 * l]);
            float4 xq = *reinterpret_cast<const float4*>(&s.xn[w][d][0]); // broadcast
            const float* xr = reinterpret_cast<const float*>(&xq);
            const float* wr = reinterpret_cast<const float*>(&wv);
            #pragma unroll
            for (int r = 0; r < RPW; r++)
                #pragma unroll
                for (int j = 0; j < 4; j++)
                    acc1[r][j] = fmaf(xr[r], wr[j], acc1[r][j]);
        }

        // ---- bias + exact GELU, stash h rows in smem ----
        #pragma unroll
        for (int r = 0; r < RPW; r++) {
            float4 hv;
            hv.x = gelu_exact(acc1[r][0] + b1v.x);
            hv.y = gelu_exact(acc1[r][1] + b1v.y);
            hv.z = gelu_exact(acc1[r][2] + b1v.z);
            hv.w = gelu_exact(acc1[r][3] + b1v.w);
            *reinterpret_cast<float4*>(&s.h[w][r][4 * l]) = hv;
        }
        __syncwarp();

        // ---- GEMM2: out[r][q] = h[r] @ w2, lane l owns q in [4l, 4l+4) ----
        float acc2[RPW][4];
        #pragma unroll
        for (int r = 0; r < RPW; r++)
            #pragma unroll
            for (int j = 0; j < 4; j++) acc2[r][j] = 0.0f;

        #pragma unroll 4
        for (int p0 = 0; p0 < NDP; p0 += 4) {
            float4 hq[RPW];
            #pragma unroll
            for (int r = 0; r < RPW; r++)
                hq[r] = *reinterpret_cast<const float4*>(&s.h[w][r][p0]); // broadcast
            float4 wq[4];
            #pragma unroll
            for (int k = 0; k < 4; k++)
                wq[k] = *reinterpret_cast<const float4*>(&s.w2[p0 + k][4 * l]);
            #pragma unroll
            for (int k = 0; k < 4; k++) {
                const float* wr = reinterpret_cast<const float*>(&wq[k]);
                #pragma unroll
                for (int r = 0; r < RPW; r++) {
                    const float hval = reinterpret_cast<const float*>(&hq[r])[k];
                    #pragma unroll
                    for (int j = 0; j < 4; j++)
                        acc2[r][j] = fmaf(hval, wr[j], acc2[r][j]);
                }
            }
        }

        // ---- epilogue: +b2, coalesced float4 stores ----
        #pragma unroll
        for (int r = 0; r < RPW; r++) {
            float4 o;
            o.x = acc2[r][0] + b2v.x;
            o.y = acc2[r][1] + b2v.y;
            o.z = acc2[r][2] + b2v.z;
            o.w = acc2[r][3] + b2v.w;
            *reinterpret_cast<float4*>(&out[(base + r) * NDP + 4 * l]) = o;
        }
    }
}

extern "C" void kernel_launch(void* const* d_in, const int* in_sizes, int n_in,
                              void* d_out, int out_size) {
    (void)in_sizes; (void)n_in; (void)out_size;
    const float* x    = (const float*)d_in[0];
    const float* ln_g = (const float*)d_in[1];
    const float* ln_b = (const float*)d_in[2];
    const float* w1   = (const float*)d_in[3];
    const float* b1   = (const float*)d_in[4];
    const float* w2   = (const float*)d_in[5];
    const float* b2   = (const float*)d_in[6];
    float* out = (float*)d_out;

    cudaFuncSetAttribute(ip_kernel, cudaFuncAttributeMaxDynamicSharedMemorySize,
                         (int)sizeof(Smem));
    ip_kernel<<<GRID, 256, sizeof(Smem)>>>(x, ln_g, ln_b, w1, b1, w2, b2, out);
}

// round 5
// speedup vs baseline: 2.1051x; 2.1051x over previous
#include <cuda_runtime.h>
#include <cuda_bf16.h>
#include <cstdint>
#include <math.h>

#define NDIN 25
#define NDP  128
#define NROWS (256*2048)
#define TILE_M 128
#define NTILES (NROWS/TILE_M)   // 4096
#define NTHREADS 256
#define GRID 148

// ---------------- SMEM layout (byte offsets) ----------------
#define OFF_X     0        // 12800 B  (128 rows x 25 f32)
#define OFF_XNHI  12800    // 10240 B  (128 rows x 80B: 32 bf16, 80B row stride)
#define OFF_XNLO  23040    // 10240 B
#define OFF_W1F   33280    // 16384 B  [s2][j16][t32] uint4 = (bh0,bh1,bl0,bl1)
#define OFF_W2F   49664    // 65536 B  [s8][j16][t32] uint4
#define OFF_B1    115200   // 512
#define OFF_B2    115712   // 512
#define OFF_G     116224   // 128
#define OFF_BETA  116352   // 128
#define SMEM_TOTAL 116480

__device__ __forceinline__ uint32_t smem_u32(const void* p) {
    uint32_t a;
    asm("{ .reg .u64 t; cvta.to.shared.u64 t, %1; cvt.u32.u64 %0, t; }" : "=r"(a) : "l"(p));
    return a;
}

__device__ __forceinline__ void ldsm4(uint32_t* r, uint32_t addr) {
    asm volatile("ldmatrix.sync.aligned.m8n8.x4.shared.b16 {%0,%1,%2,%3}, [%4];"
                 : "=r"(r[0]), "=r"(r[1]), "=r"(r[2]), "=r"(r[3]) : "r"(addr));
}

__device__ __forceinline__ void mma_bf16(float* c, const uint32_t* a, uint32_t b0, uint32_t b1) {
    asm volatile("mma.sync.aligned.m16n8k16.row.col.f32.bf16.bf16.f32 "
                 "{%0,%1,%2,%3}, {%4,%5,%6,%7}, {%8,%9}, {%0,%1,%2,%3};"
                 : "+f"(c[0]), "+f"(c[1]), "+f"(c[2]), "+f"(c[3])
                 : "r"(a[0]), "r"(a[1]), "r"(a[2]), "r"(a[3]), "r"(b0), "r"(b1));
}

__device__ __forceinline__ void cp16(uint32_t saddr, const void* g) {
    asm volatile("cp.async.ca.shared.global [%0], [%1], 16;" :: "r"(saddr), "l"(g));
}
#define CP_COMMIT() asm volatile("cp.async.commit_group;" ::: "memory")
#define CP_WAIT0()  asm volatile("cp.async.wait_group 0;" ::: "memory")

// pack two f32->bf16 into one u32: low half = first arg
__device__ __forceinline__ uint32_t pk2(float f_lo, float f_hi) {
    uint32_t r;
    asm("cvt.rn.bf16x2.f32 %0, %1, %2;" : "=r"(r) : "f"(f_hi), "f"(f_lo));
    return r;
}

// GELU with erf via Abramowitz-Stegun 7.1.26 (|eps_erf| <= 1.5e-7)
__device__ __forceinline__ float gelu_f(float v) {
    float z = fabsf(v) * 0.70710678118654752440f;
    float t = __fdividef(1.0f, fmaf(0.3275911f, z, 1.0f));
    float p = t * fmaf(t, fmaf(t, fmaf(t, fmaf(t, 1.061405429f, -1.453152027f),
                                       1.421413741f), -0.284496736f), 0.254829592f);
    float e = __expf(-z * z);
    float erfv = fmaf(-p, e, 1.0f);
    float erfs = (v < 0.0f) ? -erfv : erfv;
    return 0.5f * v * (1.0f + erfs);
}

__device__ __forceinline__ float bf16_resid(float v) {
    __nv_bfloat16 h = __float2bfloat16_rn(v);
    return v - __bfloat162float(h);
}

__global__ __launch_bounds__(NTHREADS, 1)
void ip_mma_kernel(const float* __restrict__ x,
                   const float* __restrict__ ln_g,
                   const float* __restrict__ ln_b,
                   const float* __restrict__ w1,
                   const float* __restrict__ b1,
                   const float* __restrict__ w2,
                   const float* __restrict__ b2,
                   float* __restrict__ out) {
    extern __shared__ char smem[];
    const uint32_t sb = smem_u32(smem);
    const int tid = threadIdx.x;
    const int lane = tid & 31;
    const int wid = tid >> 5;

    float* b1s = reinterpret_cast<float*>(smem + OFF_B1);
    float* b2s = reinterpret_cast<float*>(smem + OFF_B2);
    float* gs  = reinterpret_cast<float*>(smem + OFF_G);
    float* bs  = reinterpret_cast<float*>(smem + OFF_BETA);

    if (tid < 128) { b1s[tid] = b1[tid]; b2s[tid] = b2[tid]; }
    if (tid < NDIN) { gs[tid] = ln_g[tid]; bs[tid] = ln_b[tid]; }

    // ---- stage w1 fragments: B[n][k]=w1[k][n], interleaved hi/lo uint4 ----
    uint4* w1f = reinterpret_cast<uint4*>(smem + OFF_W1F);
    for (int idx = tid; idx < 2 * 16 * 32; idx += NTHREADS) {
        int t = idx & 31, j = (idx >> 5) & 15, s = idx >> 9;
        int n = 8 * j + (t >> 2);
        int k0 = 16 * s + 2 * (t & 3);
        int kk[4] = {k0, k0 + 1, k0 + 8, k0 + 9};
        float v[4], r[4];
        #pragma unroll
        for (int q = 0; q < 4; q++) {
            v[q] = (kk[q] < NDIN) ? w1[kk[q] * NDP + n] : 0.0f;
            r[q] = bf16_resid(v[q]);
        }
        uint4 val;
        val.x = pk2(v[0], v[1]);
        val.y = pk2(v[2], v[3]);
        val.z = pk2(r[0], r[1]);
        val.w = pk2(r[2], r[3]);
        w1f[(s * 16 + j) * 32 + t] = val;
    }
    // ---- stage w2 fragments: B[n][k]=w2[k][n], interleaved hi/lo uint4 ----
    uint4* w2f = reinterpret_cast<uint4*>(smem + OFF_W2F);
    for (int idx = tid; idx < 8 * 16 * 32; idx += NTHREADS) {
        int t = idx & 31, j = (idx >> 5) & 15, s = idx >> 9;
        int n = 8 * j + (t >> 2);
        int k0 = 16 * s + 2 * (t & 3);
        float v0 = w2[k0 * NDP + n],       v1 = w2[(k0 + 1) * NDP + n];
        float v2 = w2[(k0 + 8) * NDP + n], v3 = w2[(k0 + 9) * NDP + n];
        uint4 val;
        val.x = pk2(v0, v1);
        val.y = pk2(v2, v3);
        val.z = pk2(bf16_resid(v0), bf16_resid(v1));
        val.w = pk2(bf16_resid(v2), bf16_resid(v3));
        w2f[(s * 16 + j) * 32 + t] = val;
    }
    __syncthreads();

    // per-warp ldmatrix base addresses for xn A-frags (16-row strip)
    const int m0 = wid * 16;
    const uint32_t addrAh = sb + OFF_XNHI + (uint32_t)(m0 + (lane & 15)) * 80 + ((lane >> 4) & 1) * 16;
    const uint32_t addrAl = sb + OFF_XNLO + (uint32_t)(m0 + (lane & 15)) * 80 + ((lane >> 4) & 1) * 16;

    // ---- prologue: prefetch first x tile ----
    {
        const char* src = reinterpret_cast<const char*>(x) + (size_t)blockIdx.x * TILE_M * NDIN * 4;
        #pragma unroll
        for (int k = 0; k < 4; k++) {
            int idx = tid + NTHREADS * k;
            if (idx < 800) cp16(sb + OFF_X + idx * 16, src + idx * 16);
        }
        CP_COMMIT();
    }

    for (int t = blockIdx.x; t < NTILES; t += GRID) {
        CP_WAIT0();
        __syncthreads();   // x tile ready; prior iter's xn reads done

        // ---- LayerNorm + bf16 split -> xn SMEM (threads 0..127, one row each) ----
        if (tid < 128) {
            const float* xr = reinterpret_cast<const float*>(smem + OFF_X) + tid * NDIN;
            float xv[NDIN];
            float s = 0.0f;
            #pragma unroll
            for (int k = 0; k < NDIN; k++) { xv[k] = xr[k]; s += xv[k]; }
            float mu = s * (1.0f / NDIN);
            float vv = 0.0f;
            #pragma unroll
            for (int k = 0; k < NDIN; k++) { float d = xv[k] - mu; vv += d * d; }
            float rstd = rsqrtf(vv * (1.0f / NDIN) + 1e-5f);
            uint32_t* dh = reinterpret_cast<uint32_t*>(smem + OFF_XNHI + tid * 80);
            uint32_t* dl = reinterpret_cast<uint32_t*>(smem + OFF_XNLO + tid * 80);
            #pragma unroll
            for (int c = 0; c < 16; c++) {
                int k0 = 2 * c, k1 = 2 * c + 1;
                float e0 = (k0 < NDIN) ? (xv[k0] - mu) * rstd * gs[k0] + bs[k0] : 0.0f;
                float e1 = (k1 < NDIN) ? (xv[k1] - mu) * rstd * gs[k1] + bs[k1] : 0.0f;
                dh[c] = pk2(e0, e1);
                dl[c] = pk2(bf16_resid(e0), bf16_resid(e1));
            }
        }
        __syncthreads();   // xn ready; x buffer free

        // ---- prefetch next x tile (overlaps all MMA work) ----
        {
            int tn = t + GRID;
            if (tn < NTILES) {
                const char* src = reinterpret_cast<const char*>(x) + (size_t)tn * TILE_M * NDIN * 4;
                #pragma unroll
                for (int k = 0; k < 4; k++) {
                    int idx = tid + NTHREADS * k;
                    if (idx < 800) cp16(sb + OFF_X + idx * 16, src + idx * 16);
                }
            }
            CP_COMMIT();
        }

        // ---- GEMM1: acc = xn @ w1 (3-term bf16 split), per-warp M=16 strip ----
        uint32_t ah[8], al[8];
        ldsm4(ah + 0, addrAh);      ldsm4(ah + 4, addrAh + 32);
        ldsm4(al + 0, addrAl);      ldsm4(al + 4, addrAl + 32);

        float acc[16][4];
        #pragma unroll
        for (int j = 0; j < 16; j++)
            #pragma unroll
            for (int r = 0; r < 4; r++) acc[j][r] = 0.0f;

        const uint4* f1 = reinterpret_cast<const uint4*>(smem + OFF_W1F);
        #pragma unroll
        for (int j = 0; j < 16; j++) {
            #pragma unroll
            for (int s = 0; s < 2; s++) {
                uint4 b = f1[(s * 16 + j) * 32 + lane];
                mma_bf16(acc[j], ah + 4 * s, b.x, b.y);
                mma_bf16(acc[j], ah + 4 * s, b.z, b.w);
                mma_bf16(acc[j], al + 4 * s, b.x, b.y);
            }
        }

        // ---- bias + GELU + split: C frags -> GEMM2 A frags (registers only) ----
        uint32_t a2h[8][4], a2l[8][4];
        #pragma unroll
        for (int j = 0; j < 16; j++) {
            const float2 bb = *reinterpret_cast<const float2*>(b1s + 8 * j + 2 * (lane & 3));
            float g0 = gelu_f(acc[j][0] + bb.x);
            float g1 = gelu_f(acc[j][1] + bb.y);
            float g2 = gelu_f(acc[j][2] + bb.x);
            float g3 = gelu_f(acc[j][3] + bb.y);
            int s = j >> 1, h = (j & 1) * 2;
            a2h[s][h + 0] = pk2(g0, g1);
            a2h[s][h + 1] = pk2(g2, g3);
            a2l[s][h + 0] = pk2(bf16_resid(g0), bf16_resid(g1));
            a2l[s][h + 1] = pk2(bf16_resid(g2), bf16_resid(g3));
        }

        // ---- GEMM2 in two j-halves (lower regs, stores overlap 2nd half) ----
        const uint4* f2 = reinterpret_cast<const uint4*>(smem + OFF_W2F);
        const size_t row0 = (size_t)t * TILE_M + m0 + (lane >> 2);
        #pragma unroll
        for (int half = 0; half < 2; half++) {
            float acc2[8][4];
            #pragma unroll
            for (int j = 0; j < 8; j++)
                #pragma unroll
                for (int r = 0; r < 4; r++) acc2[j][r] = 0.0f;

            #pragma unroll
            for (int j8 = 0; j8 < 8; j8++) {
                int j = 8 * half + j8;
                #pragma unroll
                for (int s = 0; s < 8; s++) {
                    uint4 b = f2[(s * 16 + j) * 32 + lane];
                    mma_bf16(acc2[j8], a2h[s], b.x, b.y);
                    mma_bf16(acc2[j8], a2h[s], b.z, b.w);
                    mma_bf16(acc2[j8], a2l[s], b.x, b.y);
                }
            }

            // epilogue for this half: +b2, float2 stores
            #pragma unroll
            for (int j8 = 0; j8 < 8; j8++) {
                int j = 8 * half + j8;
                const float2 bb = *reinterpret_cast<const float2*>(b2s + 8 * j + 2 * (lane & 3));
                int col = 8 * j + 2 * (lane & 3);
                float2 o0 = make_float2(acc2[j8][0] + bb.x, acc2[j8][1] + bb.y);
                float2 o1 = make_float2(acc2[j8][2] + bb.x, acc2[j8][3] + bb.y);
                *reinterpret_cast<float2*>(out + row0 * NDP + col) = o0;
                *reinterpret_cast<float2*>(out + (row0 + 8) * NDP + col) = o1;
            }
        }
    }
}

extern "C" void kernel_launch(void* const* d_in, const int* in_sizes, int n_in,
                              void* d_out, int out_size) {
    (void)in_sizes; (void)n_in; (void)out_size;
    const float* x    = (const float*)d_in[0];
    const float* ln_g = (const float*)d_in[1];
    const float* ln_b = (const float*)d_in[2];
    const float* w1   = (const float*)d_in[3];
    const float* b1   = (const float*)d_in[4];
    const float* w2   = (const float*)d_in[5];
    const float* b2   = (const float*)d_in[6];
    float* out = (float*)d_out;

    cudaFuncSetAttribute(ip_mma_kernel, cudaFuncAttributeMaxDynamicSharedMemorySize, SMEM_TOTAL);
    ip_mma_kernel<<<GRID, NTHREADS, SMEM_TOTAL>>>(x, ln_g, ln_b, w1, b1, w2, b2, out);
}